// round 1
// baseline (speedup 1.0000x reference)
#include <cuda_runtime.h>
#include <cstddef>

// Problem constants (B=64, T=2048, J=24, C=4*J+3=99)
#define NB 64
#define NT 2048
#define NJ 24
#define NC 99
#define TPB 128
#define GX (NT / TPB)          // 16
#define NBLK (GX * NB)         // 1024 partials

__device__ float g_partials[NBLK];

__device__ __forceinline__ float warp_sum(float v) {
#pragma unroll
    for (int o = 16; o > 0; o >>= 1) v += __shfl_down_sync(0xffffffffu, v, o);
    return v;
}

__device__ __forceinline__ void quat2mat(const float q[4], float m[9]) {
    const float w = q[0], x = q[1], y = q[2], z = q[3];
    const float s = 2.0f / (w * w + x * x + y * y + z * z);
    m[0] = 1.0f - s * (y * y + z * z);
    m[1] = s * (x * y - z * w);
    m[2] = s * (x * z + y * w);
    m[3] = s * (x * y + z * w);
    m[4] = 1.0f - s * (x * x + z * z);
    m[5] = s * (y * z - x * w);
    m[6] = s * (x * z - y * w);
    m[7] = s * (y * z + x * w);
    m[8] = 1.0f - s * (x * x + y * y);
}

__device__ __forceinline__ void mat3mul(const float a[9], const float b[9], float c[9]) {
#pragma unroll
    for (int r = 0; r < 3; r++)
#pragma unroll
        for (int cc = 0; cc < 3; cc++)
            c[r * 3 + cc] = a[r * 3 + 0] * b[0 * 3 + cc]
                          + a[r * 3 + 1] * b[1 * 3 + cc]
                          + a[r * 3 + 2] * b[2 * 3 + cc];
}

__global__ void __launch_bounds__(TPB) motion_loss_kernel(
    const float* __restrict__ Ym, const float* __restrict__ Xm,
    const float* __restrict__ Yt, const float* __restrict__ Xt,
    const float* __restrict__ jw)
{
    __shared__ float sw[NJ];
    __shared__ float soY[NJ * 3];
    __shared__ float soX[NJ * 3];

    const int b   = blockIdx.y;
    const int t   = blockIdx.x * TPB + threadIdx.x;
    const int tid = threadIdx.x;

    if (tid < NJ) sw[tid] = jw[tid];
    if (tid < NJ * 3) {
        soY[tid] = Yt[b * NJ * 3 + tid];
        soX[tid] = Xt[b * NJ * 3 + tid];
    }
    __syncthreads();

    const float* yb = Ym + (size_t)b * NC * NT + t;
    const float* xb = Xm + (size_t)b * NC * NT + t;

    float lrot = 0.0f, lfk = 0.0f;

    // FK register state: at most 3 live (transform, result) pairs at any step.
    float TsY[3][9], TsX[3][9];
    float RsY[3][3], RsX[3][3];

    // TOPOLOGY = {-1,0,0,0,1,2,3,4,5,6,7,8,9,9,9,12,13,14,16,17,18,19,20,21}
    // SLOT[i]  = storage slot for joint i's transform/result (-1 for leaves)
    // PSLOT[i] = slot holding joint i's parent state at processing time
    constexpr int SLOT[NJ]  = {0,1,2,0,1,2,0,1,2,0,-1,-1,1,2,0,-1,1,2,0,1,2,0,-1,-1};
    constexpr int PSLOT[NJ] = {-1,0,0,0,1,2,0,1,2,0,1,2,0,0,0,1,2,0,1,2,0,1,2,0};

#pragma unroll
    for (int i = 0; i < NJ; i++) {
        const float wj = sw[i];

        float qy[4], qx[4];
#pragma unroll
        for (int k = 0; k < 4; k++) {
            qy[k] = yb[(size_t)(4 * i + k) * NT];
            qx[k] = xb[(size_t)(4 * i + k) * NT];
            lrot += wj * fabsf(qy[k] - qx[k]);
        }

        float my[9], mx[9];
        quat2mat(qy, my);
        quat2mat(qx, mx);

        float cy[9], cx[9];
        if (i == 0) {
#pragma unroll
            for (int e = 0; e < 9; e++) { cy[e] = my[e]; cx[e] = mx[e]; }
        } else {
            const int ps = PSLOT[i];
            mat3mul(TsY[ps], my, cy);
            mat3mul(TsX[ps], mx, cx);
        }

        float ry[3], rx[3];
#pragma unroll
        for (int r = 0; r < 3; r++) {
            ry[r] = cy[r * 3 + 0] * soY[i * 3 + 0]
                  + cy[r * 3 + 1] * soY[i * 3 + 1]
                  + cy[r * 3 + 2] * soY[i * 3 + 2];
            rx[r] = cx[r * 3 + 0] * soX[i * 3 + 0]
                  + cx[r * 3 + 1] * soX[i * 3 + 1]
                  + cx[r * 3 + 2] * soX[i * 3 + 2];
        }
        if (i > 0) {
            const int ps = PSLOT[i];
#pragma unroll
            for (int r = 0; r < 3; r++) { ry[r] += RsY[ps][r]; rx[r] += RsX[ps][r]; }
        }

        lfk += wj * (fabsf(ry[0] - rx[0]) + fabsf(ry[1] - rx[1]) + fabsf(ry[2] - rx[2]));

        if (SLOT[i] >= 0) {
            const int s = SLOT[i];
#pragma unroll
            for (int e = 0; e < 9; e++) { TsY[s][e] = cy[e]; TsX[s][e] = cx[e]; }
#pragma unroll
            for (int r = 0; r < 3; r++) { RsY[s][r] = ry[r]; RsX[s][r] = rx[r]; }
        }
    }

    float lpos = 0.0f;
#pragma unroll
    for (int d = 0; d < 3; d++)
        lpos += fabsf(yb[(size_t)(4 * NJ + d) * NT] - xb[(size_t)(4 * NJ + d) * NT]);

    // loss = B1*sum_rot/(B*T*J*4) + B2*sum_fk/(B*T*J*3) + sum_pos/(B*T*3)
    const float CR = 1.0f / (64.0f * 2048.0f * 24.0f * 4.0f);
    const float CF = 1.0f / (64.0f * 2048.0f * 24.0f * 3.0f);
    const float CP = 1.0f / (64.0f * 2048.0f * 3.0f);
    float v = lrot * CR + lfk * CF + lpos * CP;

    // Block reduction: 4 warps
    v = warp_sum(v);
    __shared__ float red[TPB / 32];
    if ((tid & 31) == 0) red[tid >> 5] = v;
    __syncthreads();
    if (tid == 0) {
        float s = 0.0f;
#pragma unroll
        for (int wgi = 0; wgi < TPB / 32; wgi++) s += red[wgi];
        g_partials[blockIdx.y * GX + blockIdx.x] = s;
    }
}

__global__ void __launch_bounds__(NBLK) reduce_kernel(float* __restrict__ out) {
    const int tid = threadIdx.x;
    float v = g_partials[tid];            // exactly NBLK=1024 threads
    v = warp_sum(v);
    __shared__ float red[32];
    if ((tid & 31) == 0) red[tid >> 5] = v;
    __syncthreads();
    if (tid < 32) {
        float s = red[tid];
        s = warp_sum(s);
        if (tid == 0) out[0] = s;
    }
}

extern "C" void kernel_launch(void* const* d_in, const int* in_sizes, int n_in,
                              void* d_out, int out_size) {
    const float* Ym = (const float*)d_in[0];
    const float* Xm = (const float*)d_in[1];
    const float* Yt = (const float*)d_in[2];
    const float* Xt = (const float*)d_in[3];
    const float* jw = (const float*)d_in[4];

    dim3 grid(GX, NB);
    motion_loss_kernel<<<grid, TPB>>>(Ym, Xm, Yt, Xt, jw);
    reduce_kernel<<<1, NBLK>>>((float*)d_out);
}

// round 3
// speedup vs baseline: 1.2953x; 1.2953x over previous
#include <cuda_runtime.h>
#include <cstddef>

// Problem constants (B=64, T=2048, J=24, C=4*J+3=99)
#define NB 64
#define NT 2048
#define NJ 24
#define NC 99
#define TPB 128
#define GX (NT / TPB)          // 16
#define NBLK (GX * NB)         // 1024 partial sums

__device__ float g_partials[NBLK];
__device__ unsigned int g_count = 0;

// ---------------- packed f32x2 helpers (Blackwell sm_100a) ----------------
typedef unsigned long long f2;

__device__ __forceinline__ f2 f2pk(float lo, float hi) {
    f2 r; asm("mov.b64 %0, {%1, %2};" : "=l"(r) : "f"(lo), "f"(hi)); return r;
}
__device__ __forceinline__ void f2un(f2 v, float& lo, float& hi) {
    asm("mov.b64 {%0, %1}, %2;" : "=f"(lo), "=f"(hi) : "l"(v));
}
__device__ __forceinline__ f2 f2add(f2 a, f2 b) {
    f2 r; asm("add.rn.f32x2 %0, %1, %2;" : "=l"(r) : "l"(a), "l"(b)); return r;
}
__device__ __forceinline__ f2 f2neg(f2 a) {
    f2 r; asm("xor.b64 %0, %1, 0x8000000080000000;" : "=l"(r) : "l"(a)); return r;
}
__device__ __forceinline__ f2 f2sub(f2 a, f2 b) {       // a - b == a + (-b), exact
    return f2add(a, f2neg(b));
}
__device__ __forceinline__ f2 f2mul(f2 a, f2 b) {
    f2 r; asm("mul.rn.f32x2 %0, %1, %2;" : "=l"(r) : "l"(a), "l"(b)); return r;
}
__device__ __forceinline__ f2 f2fma(f2 a, f2 b, f2 c) {
    f2 r; asm("fma.rn.f32x2 %0, %1, %2, %3;" : "=l"(r) : "l"(a), "l"(b), "l"(c)); return r;
}
__device__ __forceinline__ float frcp(float x) {
    float r; asm("rcp.approx.f32 %0, %1;" : "=f"(r) : "f"(x)); return r;
}

__device__ __forceinline__ float warp_sum(float v) {
#pragma unroll
    for (int o = 16; o > 0; o >>= 1) v += __shfl_down_sync(0xffffffffu, v, o);
    return v;
}

// quat->rotmat on a packed (Y,X) pair. q[4], m[9] all f32x2.
__device__ __forceinline__ void quat2mat2(const f2 q[4], f2 m[9]) {
    const f2 w = q[0], x = q[1], y = q[2], z = q[3];
    const f2 xx = f2mul(x, x), yy = f2mul(y, y), zz = f2mul(z, z);
    const f2 xy = f2mul(x, y), xz = f2mul(x, z), yz = f2mul(y, z);
    const f2 wx = f2mul(w, x), wy = f2mul(w, y), wz = f2mul(w, z);
    const f2 n  = f2fma(w, w, f2add(f2add(xx, yy), zz));
    float nl, nh; f2un(n, nl, nh);
    const float sl = 2.0f * frcp(nl), sh = 2.0f * frcp(nh);
    const f2 s   = f2pk(sl, sh);
    const f2 ns  = f2pk(-sl, -sh);
    const f2 one = f2pk(1.0f, 1.0f);
    m[0] = f2fma(ns, f2add(yy, zz), one);
    m[1] = f2mul(s,  f2sub(xy, wz));
    m[2] = f2mul(s,  f2add(xz, wy));
    m[3] = f2mul(s,  f2add(xy, wz));
    m[4] = f2fma(ns, f2add(xx, zz), one);
    m[5] = f2mul(s,  f2sub(yz, wx));
    m[6] = f2mul(s,  f2sub(xz, wy));
    m[7] = f2mul(s,  f2add(yz, wx));
    m[8] = f2fma(ns, f2add(xx, yy), one);
}

__device__ __forceinline__ void mat3mul2(const f2 a[9], const f2 b[9], f2 c[9]) {
#pragma unroll
    for (int r = 0; r < 3; r++)
#pragma unroll
        for (int cc = 0; cc < 3; cc++)
            c[r * 3 + cc] = f2fma(a[r * 3 + 0], b[0 * 3 + cc],
                            f2fma(a[r * 3 + 1], b[1 * 3 + cc],
                            f2mul(a[r * 3 + 2], b[2 * 3 + cc])));
}

__global__ void __launch_bounds__(TPB) motion_loss_kernel(
    const float* __restrict__ Ym, const float* __restrict__ Xm,
    const float* __restrict__ Yt, const float* __restrict__ Xt,
    const float* __restrict__ jw, float* __restrict__ out)
{
    __shared__ float sw[NJ];
    __shared__ f2    so[NJ * 3];     // packed (Yt, Xt) offsets for this batch
    __shared__ float red[TPB / 32];
    __shared__ bool  is_last;

    const int b   = blockIdx.y;
    const int t   = blockIdx.x * TPB + threadIdx.x;
    const int tid = threadIdx.x;

    if (tid < NJ) sw[tid] = jw[tid];
    if (tid < NJ * 3) so[tid] = f2pk(Yt[b * NJ * 3 + tid], Xt[b * NJ * 3 + tid]);
    __syncthreads();

    const float* yb = Ym + (size_t)b * NC * NT + t;
    const float* xb = Xm + (size_t)b * NC * NT + t;

    float lrot = 0.0f, lfk = 0.0f;

    // FK register state: at most 3 live (transform, result) pairs at any step.
    f2 Ts[3][9];
    f2 Rs[3][3];

    // TOPOLOGY = {-1,0,0,0,1,2,3,4,5,6,7,8,9,9,9,12,13,14,16,17,18,19,20,21}
    constexpr int SLOT[NJ]  = {0,1,2,0,1,2,0,1,2,0,-1,-1,1,2,0,-1,1,2,0,1,2,0,-1,-1};
    constexpr int PSLOT[NJ] = {-1,0,0,0,1,2,0,1,2,0,1,2,0,0,0,1,2,0,1,2,0,1,2,0};

#pragma unroll
    for (int i = 0; i < NJ; i++) {
        const float wj = sw[i];

        f2 q[4];
#pragma unroll
        for (int k = 0; k < 4; k++) {
            const float a = yb[(size_t)(4 * i + k) * NT];
            const float c = xb[(size_t)(4 * i + k) * NT];
            lrot += wj * fabsf(a - c);
            q[k] = f2pk(a, c);
        }

        f2 m[9];
        quat2mat2(q, m);

        f2 c[9];
        if (i == 0) {
#pragma unroll
            for (int e = 0; e < 9; e++) c[e] = m[e];
        } else {
            mat3mul2(Ts[PSLOT[i]], m, c);
        }

        f2 r[3];
#pragma unroll
        for (int rr = 0; rr < 3; rr++)
            r[rr] = f2fma(c[rr * 3 + 2], so[i * 3 + 2],
                    f2fma(c[rr * 3 + 1], so[i * 3 + 1],
                    f2mul(c[rr * 3 + 0], so[i * 3 + 0])));
        if (i > 0) {
            const int ps = PSLOT[i];
#pragma unroll
            for (int rr = 0; rr < 3; rr++) r[rr] = f2add(r[rr], Rs[ps][rr]);
        }

        float fkd = 0.0f;
#pragma unroll
        for (int rr = 0; rr < 3; rr++) {
            float ylo, xhi; f2un(r[rr], ylo, xhi);
            fkd += fabsf(ylo - xhi);
        }
        lfk += wj * fkd;

        if (SLOT[i] >= 0) {
            const int s = SLOT[i];
#pragma unroll
            for (int e = 0; e < 9; e++) Ts[s][e] = c[e];
#pragma unroll
            for (int rr = 0; rr < 3; rr++) Rs[s][rr] = r[rr];
        }
    }

    float lpos = 0.0f;
#pragma unroll
    for (int d = 0; d < 3; d++)
        lpos += fabsf(yb[(size_t)(4 * NJ + d) * NT] - xb[(size_t)(4 * NJ + d) * NT]);

    // loss = B1*sum_rot/(B*T*J*4) + B2*sum_fk/(B*T*J*3) + sum_pos/(B*T*3)
    const float CR = 1.0f / (64.0f * 2048.0f * 24.0f * 4.0f);
    const float CF = 1.0f / (64.0f * 2048.0f * 24.0f * 3.0f);
    const float CP = 1.0f / (64.0f * 2048.0f * 3.0f);
    float v = lrot * CR + lfk * CF + lpos * CP;

    // ---- block reduction ----
    v = warp_sum(v);
    if ((tid & 31) == 0) red[tid >> 5] = v;
    __syncthreads();
    if (tid == 0) {
        float s = 0.0f;
#pragma unroll
        for (int wgi = 0; wgi < TPB / 32; wgi++) s += red[wgi];
        g_partials[blockIdx.y * GX + blockIdx.x] = s;
        __threadfence();
        const unsigned int old = atomicAdd(&g_count, 1u);
        is_last = (old == NBLK - 1);
    }
    __syncthreads();

    // ---- last block folds all partials (deterministic fixed-order sum) ----
    if (is_last) {
        float s = 0.0f;
#pragma unroll
        for (int k = 0; k < NBLK / TPB; k++) s += g_partials[tid + k * TPB];
        s = warp_sum(s);
        if ((tid & 31) == 0) red[tid >> 5] = s;
        __syncthreads();
        if (tid == 0) {
            float tot = 0.0f;
#pragma unroll
            for (int wgi = 0; wgi < TPB / 32; wgi++) tot += red[wgi];
            out[0] = tot;
            g_count = 0;   // reset for next graph replay
        }
    }
}

extern "C" void kernel_launch(void* const* d_in, const int* in_sizes, int n_in,
                              void* d_out, int out_size) {
    const float* Ym = (const float*)d_in[0];
    const float* Xm = (const float*)d_in[1];
    const float* Yt = (const float*)d_in[2];
    const float* Xt = (const float*)d_in[3];
    const float* jw = (const float*)d_in[4];

    dim3 grid(GX, NB);
    motion_loss_kernel<<<grid, TPB>>>(Ym, Xm, Yt, Xt, jw, (float*)d_out);
}